// round 11
// baseline (speedup 1.0000x reference)
#include <cuda_runtime.h>
#include <cstdint>

// GCNStage4_ReduceSum: out[t] += msg[e] for t = edge_index[1][e]
// msg: [NUM_EDGES, 32] f32; edge_index: [2, NUM_EDGES] int32 (harness); out: [num_nodes, 32] f32
//
// R11: hybrid RMW-path experiment. First half of edges via REDG v4 atomics
// (R5 shape, best measured), second half via 128B cp.reduce.async.bulk (R10
// shape), in ONE kernel with block-range specialization so both streams hit
// L2 concurrently. Discriminates "shared per-16B L2 atomic ALU" (flat ~47-50)
// vs "independent / coarser-granularity bulk path" (~40-44).

#define FEAT   32
#define WARPS  8
#define E      16    // edges per warp-stage (bulk path)
#define ITERS  4     // 64 edges per warp (bulk path)
#define EDGES_PER_BULK_BLOCK (WARPS * E * ITERS)   // 512
#define FRAGS_PER_ATOMIC_BLOCK 1024                // 256 thr x 4 unroll

__global__ void __launch_bounds__(256) scatter_hybrid_kernel(
        const float4* __restrict__ msg4,
        const int* __restrict__ tgt,
        float* __restrict__ out,
        int num_atomic_blocks,
        int num_atomic_frags,    // atomic_edges * 8
        int bulk_edge_start,     // first edge handled by bulk path
        int num_edges)
{
    __shared__ __align__(128) float4 buf[WARPS][2][E][8];

    int tid = threadIdx.x;

    if ((int)blockIdx.x < num_atomic_blocks) {
        // ---------------- atomic REDG path (R5 shape) ----------------
        int base = blockIdx.x * FRAGS_PER_ATOMIC_BLOCK + tid;
        int e0   = base >> 3;
        int sub  = tid & 7;
        int off  = sub * 4;
        const float4* src = msg4 + (size_t)e0 * 8 + sub;

        int    t[4];
        float4 v[4];
        #pragma unroll
        for (int u = 0; u < 4; u++) {
            int id = base + 256 * u;
            if (id < num_atomic_frags) {
                t[u] = tgt[e0 + 32 * u];
                v[u] = __ldcs(src + 256 * u);
            }
        }
        #pragma unroll
        for (int u = 0; u < 4; u++) {
            int id = base + 256 * u;
            if (id < num_atomic_frags) {
                float* dst = out + (size_t)t[u] * FEAT + off;
                asm volatile("red.global.add.v4.f32 [%0], {%1, %2, %3, %4};"
                             :: "l"(dst), "f"(v[u].x), "f"(v[u].y), "f"(v[u].z), "f"(v[u].w)
                             : "memory");
            }
        }
        return;
    }

    // ---------------- bulk reduction path (R10 shape) ----------------
    int bb   = (int)blockIdx.x - num_atomic_blocks;
    int wid  = tid >> 5;
    int lane = tid & 31;
    int grp  = lane >> 3;
    int sub  = lane & 7;
    int warp_base = bulk_edge_start + (bb * WARPS + wid) * (E * ITERS);

    uint32_t smem_warp;
    {
        const void* p = &buf[wid][0][0][0];
        asm("{ .reg .u64 t; cvta.to.shared.u64 t, %1; cvt.u32.u64 %0, t; }"
            : "=r"(smem_warp) : "l"(p));
    }

    #pragma unroll
    for (int iter = 0; iter < ITERS; iter++) {
        int stage = iter & 1;
        if (iter >= 2 && lane < E)
            asm volatile("cp.async.bulk.wait_group.read 1;" ::: "memory");
        __syncwarp();

        int base_e = warp_base + iter * E;

        #pragma unroll
        for (int p = 0; p < 4; p++) {
            int s = p * 4 + grp;
            int e = base_e + s;
            if (e < num_edges)
                buf[wid][stage][s][sub] = __ldcs(&msg4[(size_t)e * 8 + sub]);
        }

        int t = -1;
        if (lane < E) {
            int e = base_e + lane;
            if (e < num_edges) t = tgt[e];
        }
        __syncwarp();

        if (lane < E) {
            asm volatile("fence.proxy.async.shared::cta;" ::: "memory");
            if (t >= 0) {
                uint32_t src = smem_warp + (uint32_t)stage * (E * 128) + (uint32_t)lane * 128;
                float* dst = out + (size_t)t * FEAT;
                asm volatile(
                    "cp.reduce.async.bulk.global.shared::cta.bulk_group.add.f32 "
                    "[%0], [%1], 128;"
                    :: "l"(dst), "r"(src) : "memory");
            }
            asm volatile("cp.async.bulk.commit_group;" ::: "memory");
        }
    }

    if (lane < E)
        asm volatile("cp.async.bulk.wait_group 0;" ::: "memory");
}

extern "C" void kernel_launch(void* const* d_in, const int* in_sizes, int n_in,
                              void* d_out, int out_size) {
    const float4* msg4 = (const float4*)d_in[0];
    const int*    ei   = (const int*)d_in[1];   // int32 indices
    float*        out  = (float*)d_out;

    int num_edges = in_sizes[0] / FEAT;          // 1,600,000
    const int* tgt = ei + num_edges;             // row 1 of edge_index

    // zero output (poisoned to 0xAA by harness)
    cudaMemsetAsync(d_out, 0, (size_t)out_size * sizeof(float));

    // split edges ~50/50, atomic part multiple of 128 edges (1024 frags/block)
    int atomic_edges = (num_edges / 2) & ~127;               // 800,000
    int num_atomic_frags  = atomic_edges * 8;                // 6.4M
    int num_atomic_blocks = (num_atomic_frags + FRAGS_PER_ATOMIC_BLOCK - 1)
                            / FRAGS_PER_ATOMIC_BLOCK;        // 6250
    int bulk_edges  = num_edges - atomic_edges;              // 800,000
    int bulk_blocks = (bulk_edges + EDGES_PER_BULK_BLOCK - 1)
                      / EDGES_PER_BULK_BLOCK;                // 1563

    scatter_hybrid_kernel<<<num_atomic_blocks + bulk_blocks, 256>>>(
        msg4, tgt, out,
        num_atomic_blocks, num_atomic_frags,
        atomic_edges, num_edges);
}

// round 12
// speedup vs baseline: 1.0827x; 1.0827x over previous
#include <cuda_runtime.h>
#include <cstdint>

// GCNStage4_ReduceSum: out[t] += msg[e] for t = edge_index[1][e]
// msg: [NUM_EDGES, 32] f32; edge_index: [2, NUM_EDGES] int32 (harness); out: [num_nodes, 32] f32
//
// R12 (final): atomic scatter at the validated L2 fp-RMW roofline.
// Six structural variants (occupancy sweep, pipelining, gather, TMA bulk
// reduce, hybrid) all confirmed the ~46.5us wall = 12.8M x 16B L2 RMW ops.
// This is the best-measured shape: front-batched unroll-4, contiguous lanes
// (8 lanes = one 128B edge row -> 4-line RED.128), fire-and-forget
// red.global.add.v4.f32, guard-free main + generic tail.

#define FEAT 32
#define UNROLL 4
#define TPB 512
#define FRAGS_PER_BLOCK (TPB * UNROLL)   // 2048

__global__ void __launch_bounds__(TPB) scatter_add_main(
        const float4* __restrict__ msg4,
        const int* __restrict__ tgt,
        float* __restrict__ out)
{
    int tid  = threadIdx.x;
    int base = blockIdx.x * FRAGS_PER_BLOCK + tid;
    int e0   = base >> 3;
    int sub  = tid & 7;                   // TPB % 8 == 0 -> invariant across u
    int off  = sub * 4;
    const float4* src = msg4 + (size_t)e0 * 8 + sub;

    // Phase 1: front-batched loads (4 tgt + 4 LDG.128 in flight, MLP~8)
    int t0 = tgt[e0];
    int t1 = tgt[e0 + (TPB >> 3)];
    int t2 = tgt[e0 + 2 * (TPB >> 3)];
    int t3 = tgt[e0 + 3 * (TPB >> 3)];
    float4 v0 = __ldcs(src);
    float4 v1 = __ldcs(src + TPB);
    float4 v2 = __ldcs(src + 2 * TPB);
    float4 v3 = __ldcs(src + 3 * TPB);

    // Phase 2: fire-and-forget vector reductions (resolve at L2)
    asm volatile("red.global.add.v4.f32 [%0], {%1, %2, %3, %4};"
                 :: "l"(out + (size_t)t0 * FEAT + off), "f"(v0.x), "f"(v0.y), "f"(v0.z), "f"(v0.w) : "memory");
    asm volatile("red.global.add.v4.f32 [%0], {%1, %2, %3, %4};"
                 :: "l"(out + (size_t)t1 * FEAT + off), "f"(v1.x), "f"(v1.y), "f"(v1.z), "f"(v1.w) : "memory");
    asm volatile("red.global.add.v4.f32 [%0], {%1, %2, %3, %4};"
                 :: "l"(out + (size_t)t2 * FEAT + off), "f"(v2.x), "f"(v2.y), "f"(v2.z), "f"(v2.w) : "memory");
    asm volatile("red.global.add.v4.f32 [%0], {%1, %2, %3, %4};"
                 :: "l"(out + (size_t)t3 * FEAT + off), "f"(v3.x), "f"(v3.y), "f"(v3.z), "f"(v3.w) : "memory");
}

// Tail: one thread per remaining fragment (generic shapes).
__global__ void __launch_bounds__(256) scatter_add_tail(
        const float4* __restrict__ msg4,
        const int* __restrict__ tgt,
        float* __restrict__ out,
        int frag_start, int num_frags)
{
    int id = frag_start + blockIdx.x * blockDim.x + threadIdx.x;
    if (id >= num_frags) return;
    int e = id >> 3, sub = id & 7;
    int t = tgt[e];
    float4 v = __ldcs(&msg4[(size_t)e * 8 + sub]);
    float* dst = out + (size_t)t * FEAT + sub * 4;
    asm volatile("red.global.add.v4.f32 [%0], {%1, %2, %3, %4};"
                 :: "l"(dst), "f"(v.x), "f"(v.y), "f"(v.z), "f"(v.w) : "memory");
}

extern "C" void kernel_launch(void* const* d_in, const int* in_sizes, int n_in,
                              void* d_out, int out_size) {
    const float4* msg4 = (const float4*)d_in[0];
    const int*    ei   = (const int*)d_in[1];   // int32 indices
    float*        out  = (float*)d_out;

    int num_edges = in_sizes[0] / FEAT;          // 1,600,000
    const int* tgt = ei + num_edges;             // row 1 of edge_index

    // 1) zero the output (poisoned to 0xAA by harness); memset is capturable
    cudaMemsetAsync(d_out, 0, (size_t)out_size * sizeof(float));

    // 2) scatter-add: guard-free main (2048 frags/block) + generic tail
    int num_frags   = num_edges * 8;             // 12.8M
    int full_blocks = num_frags / FRAGS_PER_BLOCK;   // 6250 exact here
    int rem_start   = full_blocks * FRAGS_PER_BLOCK;
    if (full_blocks > 0)
        scatter_add_main<<<full_blocks, TPB>>>(msg4, tgt, out);
    int rem = num_frags - rem_start;
    if (rem > 0)
        scatter_add_tail<<<(rem + 255) / 256, 256>>>(msg4, tgt, out, rem_start, num_frags);
}

// round 13
// speedup vs baseline: 1.0915x; 1.0081x over previous
#include <cuda_runtime.h>
#include <cstdint>

// GCNStage4_ReduceSum: out[t] += msg[e] for t = edge_index[1][e]
// msg: [NUM_EDGES, 32] f32; edge_index: [2, NUM_EDGES] int32 (harness); out: [num_nodes, 32] f32
//
// FINAL (R13 = best-measured R3 shape): atomic scatter at the validated L2
// fp-RMW roofline. Seven structural variants (MLP sweep, occupancy sweep,
// lane relayout, software pipeline, ELL gather, TMA cp.reduce.async.bulk,
// hybrid concurrent paths) all converge to the ~46.5us scatter wall =
// 12.8M x 16B fp-add RMW ops at the shared L2 atomic ALU; DRAM traffic is
// exactly the compulsory 228MB. This configuration measured fastest (twice).
//
// Shape: 8 lanes = one 128B edge row (RED.128 warp-op touches 4 lines),
// unroll-4 grid-stride with front-batched loads (MLP~8 per thread),
// fire-and-forget red.global.add.v4.f32, cudaMemsetAsync zero-fill.

#define FEAT 32
#define UNROLL 4

__global__ void __launch_bounds__(256) scatter_add_kernel(
        const float4* __restrict__ msg4,
        const int* __restrict__ tgt,
        float* __restrict__ out,
        int num_frags)   // num_edges * 8
{
    int tid = blockIdx.x * blockDim.x + threadIdx.x;
    int stride = gridDim.x * blockDim.x;

    int   t[UNROLL];
    float4 v[UNROLL];
    int   id[UNROLL];

    // Phase 1: issue all loads (front-batched -> high MLP)
    #pragma unroll
    for (int u = 0; u < UNROLL; u++) {
        id[u] = tid + u * stride;
        if (id[u] < num_frags) {
            int e   = id[u] >> 3;
            int sub = id[u] & 7;
            t[u] = tgt[e];                                   // broadcast across 8 lanes
            v[u] = __ldcs(&msg4[(size_t)e * 8 + sub]);       // coalesced 128B row
        }
    }

    // Phase 2: fire-and-forget vector reductions (resolve at L2)
    #pragma unroll
    for (int u = 0; u < UNROLL; u++) {
        if (id[u] < num_frags) {
            int sub = id[u] & 7;
            float* dst = out + (size_t)t[u] * FEAT + sub * 4;
            asm volatile("red.global.add.v4.f32 [%0], {%1, %2, %3, %4};"
                         :: "l"(dst), "f"(v[u].x), "f"(v[u].y), "f"(v[u].z), "f"(v[u].w)
                         : "memory");
        }
    }
}

extern "C" void kernel_launch(void* const* d_in, const int* in_sizes, int n_in,
                              void* d_out, int out_size) {
    const float4* msg4 = (const float4*)d_in[0];
    const int*    ei   = (const int*)d_in[1];   // int32 indices
    float*        out  = (float*)d_out;

    int num_edges = in_sizes[0] / FEAT;          // 1,600,000
    const int* tgt = ei + num_edges;             // row 1 of edge_index

    // 1) zero the output (poisoned to 0xAA by harness); memset is capturable
    cudaMemsetAsync(d_out, 0, (size_t)out_size * sizeof(float));

    // 2) scatter-add: 8 lanes per edge, 4 fragments per thread (grid-stride)
    int num_frags = num_edges * 8;                       // 12.8M
    int threads = 256;
    long long total_threads = ((long long)num_frags + UNROLL - 1) / UNROLL;
    int blocks = (int)((total_threads + threads - 1) / threads);   // 12500 exact
    scatter_add_kernel<<<blocks, threads>>>(msg4, tgt, out, num_frags);
}